// round 9
// baseline (speedup 1.0000x reference)
#include <cuda_runtime.h>
#include <math.h>

#define H 1024
#define VOCAB 50257
#define NB 148                    // persistent: one block per SM
#define NT 1024
#define TILE_ROWS 24
#define TILE_FLOATS (TILE_ROWS * H)        // 96KB per buffer
#define DYN_SMEM (2 * TILE_FLOATS * 4)     // 192KB dynamic
#define LOG_CHUNK 340             // ceil(VOCAB / NB) rows per block

// Scratch (__device__ globals — allocation-free rule)
__device__ float g_partA[8192];   // layer1: [0,4096)=Wih·x, [4096,8192)=Whh·h
__device__ float g_partB[8192];   // layer2
__device__ float2 g_pairs[NB];
__device__ unsigned g_cnt[4];
__device__ volatile unsigned g_gen[4];

// ---------------------------------------------------------------------------
__device__ __forceinline__ float sigmoidf_fast(float x) {
    return 1.f / (1.f + __expf(-x));
}

__device__ __forceinline__ void merge_pair(float& m, float& s, float m2, float s2) {
    if (m2 > m) { float t = s; s = s2 + t * __expf(m - m2); m = m2; }
    else if (m2 != -INFINITY) { s += s2 * __expf(m2 - m); }
}

// Grid-wide spin barrier (all NB blocks co-resident; gen monotonic across replays)
__device__ __forceinline__ void gsync(int b) {
    __syncthreads();
    if (threadIdx.x == 0) {
        __threadfence();
        unsigned cur = g_gen[b];
        unsigned pos = atomicAdd(&g_cnt[b], 1u);
        if (pos == NB - 1) {
            g_cnt[b] = 0;
            __threadfence();
            g_gen[b] = cur + 1;
        } else {
            while (g_gen[b] == cur) __nanosleep(32);
        }
        __threadfence();
    }
    __syncthreads();
}

// cp.async primitives (16B, L1-bypass)
__device__ __forceinline__ void cp16(float* sdst, const float* gsrc) {
    unsigned s = (unsigned)__cvta_generic_to_shared(sdst);
    asm volatile("cp.async.cg.shared.global [%0], [%1], 16;" :: "r"(s), "l"(gsrc));
}
__device__ __forceinline__ void cp_commit() {
    asm volatile("cp.async.commit_group;" ::: "memory");
}
__device__ __forceinline__ void cp_wait1() {
    asm volatile("cp.async.wait_group 1;" ::: "memory");
}
__device__ __forceinline__ void cp_wait0() {
    asm volatile("cp.async.wait_group 0;" ::: "memory");
}

__device__ __forceinline__ float warp_sum(float acc) {
#pragma unroll
    for (int o = 16; o > 0; o >>= 1) acc += __shfl_down_sync(0xffffffffu, acc, o);
    return acc;
}

// dot of smem weight row (H floats) against smem x vector; warp-collective
__device__ __forceinline__ float smem_row_dot(const float* wrow, const float4* xv, int lane) {
    const float4* w4 = (const float4*)wrow;
    float acc = 0.f;
#pragma unroll
    for (int k = 0; k < 8; k++) {
        float4 w = w4[k * 32 + lane];
        float4 x = xv[k * 32 + lane];
        acc += w.x * x.x + w.y * x.y + w.z * x.z + w.w * x.w;
    }
    return acc;
}

// LSTM elementwise for element j (torch gate order i, f, g, o)
__device__ __forceinline__ void act_phase(
        const float* __restrict__ part,
        const float* __restrict__ bih, const float* __restrict__ bhh,
        float cin, float& hout, float& cout, int j) {
    float gi = part[j]         + part[4096 + j]         + bih[j]         + bhh[j];
    float gf = part[j + H]     + part[4096 + j + H]     + bih[j + H]     + bhh[j + H];
    float gg = part[j + 2 * H] + part[4096 + j + 2 * H] + bih[j + 2 * H] + bhh[j + 2 * H];
    float go = part[j + 3 * H] + part[4096 + j + 3 * H] + bih[j + 3 * H] + bhh[j + 3 * H];
    cout = sigmoidf_fast(gf) * cin + sigmoidf_fast(gi) * tanhf(gg);
    hout = sigmoidf_fast(go) * tanhf(cout);
}

// ---------------------------------------------------------------------------
// Tile issuers: every thread copies its strided 16B chunks of the tile.
// ---------------------------------------------------------------------------
__device__ __forceinline__ void issue_contig(float* buf, const float* Wbase,
                                             long r0, int nrows, int t) {
    int nch = nrows * (H / 4);             // 16B chunks in tile
    const float* src = Wbase + r0 * H;
    for (int i = t; i < nch; i += NT) cp16(buf + i * 4, src + i * 4);
}

__device__ __forceinline__ void issue_gates(float* buf, const float* Wih,
                                            const float* Whh, int vr0,
                                            int nrows, int t) {
    int nch = nrows * (H / 4);
    for (int i = t; i < nch; i += NT) {
        int row = i >> 8;                  // 256 chunks per 4KB row
        int vr = vr0 + row;
        const float* src = ((vr < 4096) ? Wih : Whh)
                           + (long)(vr & 4095) * H + (i & 255) * 4;
        cp16(buf + i * 4, src);
    }
}

// ---------------------------------------------------------------------------
// Gates GEMV: streams the active virtual-row range [lo,hi) through smem tiles.
// vr < 4096: Wih vs sx (relu'd x).  vr >= 4096: Whh vs sh (h).
// ---------------------------------------------------------------------------
__device__ void gates_stream(const float* __restrict__ Wih,
                             const float* __restrict__ Whh,
                             const float4* sx4, const float4* sh4,
                             float* __restrict__ part,
                             float* buf0, float* buf1,
                             bool xz, bool hz, int t, int lane, int warp, int b) {
    int lo = xz ? 4096 : 0;
    int hi = hz ? 4096 : 8192;
    if (lo > hi) { lo = 0; hi = 0; }
    if (xz && hz) { lo = 0; hi = 0; }
    // zero-fill inactive rows (gtid-strided across grid; <=1 elem per thread)
    for (int i = b * NT + t; i < 8192; i += NB * NT)
        if (i < lo || i >= hi) part[i] = 0.f;

    int total = hi - lo;
    int chunk = (total + NB - 1) / NB;
    int r0 = lo + b * chunk;
    int r1 = min(hi, r0 + chunk);
    int nrows = max(0, r1 - r0);
    int ntiles = (nrows + TILE_ROWS - 1) / TILE_ROWS;
    float* bufs[2] = {buf0, buf1};

    if (ntiles > 0) issue_gates(bufs[0], Wih, Whh, r0, min(TILE_ROWS, nrows), t);
    cp_commit();
    for (int i = 0; i < ntiles; i++) {
        int tr0 = r0 + i * TILE_ROWS;
        int trows = min(TILE_ROWS, r1 - tr0);
        if (i + 1 < ntiles) {
            int nr0 = tr0 + TILE_ROWS;
            issue_gates(bufs[(i + 1) & 1], Wih, Whh, nr0, min(TILE_ROWS, r1 - nr0), t);
            cp_commit();
            cp_wait1();
        } else {
            cp_wait0();
        }
        __syncthreads();
        if (warp < trows) {
            int vr = tr0 + warp;
            float acc = smem_row_dot(bufs[i & 1] + warp * H,
                                     (vr < 4096) ? sx4 : sh4, lane);
            acc = warp_sum(acc);
            if (lane == 0) part[vr] = acc;
        }
        __syncthreads();
    }
}

// ---------------------------------------------------------------------------
// ONE persistent kernel: embed -> gates1 -> act1 -> gates2 -> act2 ->
// logits (+online softmax) -> lse -> subtract. All GEMVs cp.async-tiled.
// ---------------------------------------------------------------------------
__global__ void __launch_bounds__(NT, 1) decoder_kernel(
        const int* __restrict__ id, const float* __restrict__ h0,
        const float* __restrict__ c0, const float* __restrict__ emb,
        const float* __restrict__ Wih, const float* __restrict__ Whh,
        const float* __restrict__ bih, const float* __restrict__ bhh,
        const float* __restrict__ Wout, const float* __restrict__ bout,
        float* __restrict__ out, int write_tail) {
    extern __shared__ float dynbuf[];          // 2 x 96KB tile buffers
    float* buf0 = dynbuf;
    float* buf1 = dynbuf + TILE_FLOATS;
    __shared__ float sx[H];
    __shared__ float sh[H];
    __shared__ float2 spair[32];
    __shared__ float s_lse;
    __shared__ int s_nzx, s_nzh;

    int t = threadIdx.x, lane = t & 31, warp = t >> 5, b = blockIdx.x;
    const float4* sx4 = (const float4*)sx;
    const float4* sh4 = (const float4*)sh;

    // P0: stage relu(emb[id]) and h0; detect all-zero source vectors
    if (t == 0) { s_nzx = 0; s_nzh = 0; }
    __syncthreads();
    {
        float xv = fmaxf(emb[(long)id[0] * H + t], 0.f);
        float hv = h0[t];
        sx[t] = xv; sh[t] = hv;
        if (xv != 0.f) s_nzx = 1;
        if (hv != 0.f) s_nzh = 1;
    }
    __syncthreads();

    // P1: layer-1 gates (Whh half skipped when h0 == 0)
    gates_stream(Wih, Whh, sx4, sh4, g_partA, buf0, buf1,
                 !s_nzx, !s_nzh, t, lane, warp, b);
    gsync(0);

    // P2: act1 — redundant per block; c1 stays in a register
    float h1, c1;
    act_phase(g_partA, bih, bhh, c0[t], h1, c1, t);
    __syncthreads();
    if (t == 0) { s_nzx = 0; s_nzh = 0; }
    __syncthreads();
    {
        float xv = fmaxf(h1, 0.f);
        sx[t] = xv; sh[t] = h1;
        if (xv != 0.f) s_nzx = 1;
        if (h1 != 0.f) s_nzh = 1;
    }
    __syncthreads();

    // P3: layer-2 gates (same weights per reference)
    gates_stream(Wih, Whh, sx4, sh4, g_partB, buf0, buf1,
                 !s_nzx, !s_nzh, t, lane, warp, b);
    gsync(1);

    // P4: act2 — redundant per block; block 0 writes the (h, c) tail
    float h2, c2;
    act_phase(g_partB, bih, bhh, c1, h2, c2, t);
    __syncthreads();
    sx[t] = h2;
    if (write_tail && b == 0) {
        out[VOCAB + t]     = h2;
        out[VOCAB + H + t] = c2;
    }
    __syncthreads();

    // P5: logits — contiguous per-block chunk streamed through smem tiles
    float m = -INFINITY, s = 0.f;
    {
        int r0 = b * LOG_CHUNK;
        int r1 = min(VOCAB, r0 + LOG_CHUNK);
        int nrows = max(0, r1 - r0);
        int ntiles = (nrows + TILE_ROWS - 1) / TILE_ROWS;
        float* bufs[2] = {buf0, buf1};
        if (ntiles > 0) issue_contig(bufs[0], Wout, r0, min(TILE_ROWS, nrows), t);
        cp_commit();
        for (int i = 0; i < ntiles; i++) {
            int tr0 = r0 + i * TILE_ROWS;
            int trows = min(TILE_ROWS, r1 - tr0);
            if (i + 1 < ntiles) {
                int nr0 = tr0 + TILE_ROWS;
                issue_contig(bufs[(i + 1) & 1], Wout, nr0, min(TILE_ROWS, r1 - nr0), t);
                cp_commit();
                cp_wait1();
            } else {
                cp_wait0();
            }
            __syncthreads();
            if (warp < trows) {
                int r = tr0 + warp;
                float acc = smem_row_dot(bufs[i & 1] + warp * H, sx4, lane);
                acc = warp_sum(acc);
                if (lane == 0) {
                    float v = acc + bout[r];
                    out[r] = v;
                    merge_pair(m, s, v, 1.0f);
                }
            }
            __syncthreads();
        }
    }
    if (lane == 0) spair[warp] = make_float2(m, s);
    __syncthreads();
    if (t == 0) {
        float mm = spair[0].x, ss = spair[0].y;
#pragma unroll
        for (int wq = 1; wq < 32; wq++) merge_pair(mm, ss, spair[wq].x, spair[wq].y);
        g_pairs[b] = make_float2(mm, ss);
    }
    gsync(2);

    // P6: every block redundantly reduces g_pairs (identical order/bits),
    // then subtracts lse from its slice.
    {
        float mm = -INFINITY, ss = 0.f;
        if (t < NB) { float2 p = g_pairs[t]; mm = p.x; ss = p.y; }
#pragma unroll
        for (int o = 16; o > 0; o >>= 1) {
            float m2 = __shfl_down_sync(0xffffffffu, mm, o);
            float s2 = __shfl_down_sync(0xffffffffu, ss, o);
            merge_pair(mm, ss, m2, s2);
        }
        if (lane == 0 && warp < 5) spair[warp] = make_float2(mm, ss);
        __syncthreads();
        if (t == 0) {
            mm = spair[0].x; ss = spair[0].y;
#pragma unroll
            for (int wq = 1; wq < 5; wq++) merge_pair(mm, ss, spair[wq].x, spair[wq].y);
            s_lse = mm + logf(ss);
        }
        __syncthreads();
    }
    int i = b * LOG_CHUNK + t;
    if (t < LOG_CHUNK && i < VOCAB) out[i] -= s_lse;
}

// ---------------------------------------------------------------------------
extern "C" void kernel_launch(void* const* d_in, const int* in_sizes, int n_in,
                              void* d_out, int out_size) {
    const int*   id   = (const int*)d_in[0];
    const float* h0   = (const float*)d_in[1];
    const float* c0   = (const float*)d_in[2];
    const float* emb  = (const float*)d_in[3];
    const float* Wih  = (const float*)d_in[4];
    const float* Whh  = (const float*)d_in[5];
    const float* bih  = (const float*)d_in[6];
    const float* bhh  = (const float*)d_in[7];
    const float* Wout = (const float*)d_in[8];
    const float* bout = (const float*)d_in[9];
    float* out = (float*)d_out;

    int write_tail = (out_size >= VOCAB + 2 * H) ? 1 : 0;

    cudaFuncSetAttribute(decoder_kernel,
                         cudaFuncAttributeMaxDynamicSharedMemorySize, DYN_SMEM);
    decoder_kernel<<<NB, NT, DYN_SMEM>>>(id, h0, c0, emb, Wih, Whh, bih, bhh,
                                         Wout, bout, out, write_tail);
}

// round 10
// speedup vs baseline: 1.3228x; 1.3228x over previous
#include <cuda_runtime.h>
#include <math.h>

#define H 1024
#define VOCAB 50257
#define NB 296                  // persistent: TWO blocks per SM
#define NT 512
#define NWARPS (NB * 16)        // 4736 warps
#define FIN_CHUNK 170           // ceil(VOCAB / NB)

// Scratch (__device__ globals — allocation-free rule)
__device__ float g_partA[8192];     // layer1 partials: [0,4096)=Wih, [4096,8192)=Whh
__device__ float g_partB[8192];     // layer2 partials
__device__ float2 g_pairs[NB];
__device__ unsigned g_cnt[4];
__device__ volatile unsigned g_gen[4];

// ---------------------------------------------------------------------------
__device__ __forceinline__ float sigmoidf_fast(float x) {
    return 1.f / (1.f + __expf(-x));
}

__device__ __forceinline__ void merge_pair(float& m, float& s, float m2, float s2) {
    if (m2 > m) { float t = s; s = s2 + t * __expf(m - m2); m = m2; }
    else if (m2 != -INFINITY) { s += s2 * __expf(m2 - m); }
}

// Grid-wide spin barrier (all NB blocks co-resident by launch_bounds(512,2);
// gen monotonic across graph replays, cnt self-resets)
__device__ __forceinline__ void gsync(int b) {
    __syncthreads();
    if (threadIdx.x == 0) {
        __threadfence();
        unsigned cur = g_gen[b];
        unsigned pos = atomicAdd(&g_cnt[b], 1u);
        if (pos == NB - 1) {
            g_cnt[b] = 0;
            __threadfence();
            g_gen[b] = cur + 1;
        } else {
            while (g_gen[b] == cur) __nanosleep(32);
        }
        __threadfence();
    }
    __syncthreads();
}

// Plain 256-bit load (LDG.E.256)
struct f8 { float4 a, b; };

__device__ __forceinline__ f8 ld8(const float* p) {
    f8 v;
    asm volatile(
        "{\n\t.reg .b64 q0,q1,q2,q3;\n\t"
        "ld.global.nc.v4.b64 {q0,q1,q2,q3}, [%8];\n\t"
        "mov.b64 {%0,%1}, q0;\n\tmov.b64 {%2,%3}, q1;\n\t"
        "mov.b64 {%4,%5}, q2;\n\tmov.b64 {%6,%7}, q3;\n\t}"
        : "=f"(v.a.x), "=f"(v.a.y), "=f"(v.a.z), "=f"(v.a.w),
          "=f"(v.b.x), "=f"(v.b.y), "=f"(v.b.z), "=f"(v.b.w)
        : "l"(p));
    return v;
}

__device__ __forceinline__ void row_load(const float* W, int lane, f8 w[4]) {
#pragma unroll
    for (int k = 0; k < 4; k++) w[k] = ld8(W + (k * 32 + lane) * 8);
}

__device__ __forceinline__ float dot8(const f8& w, const float4& x0, const float4& x1) {
    return w.a.x * x0.x + w.a.y * x0.y + w.a.z * x0.z + w.a.w * x0.w
         + w.b.x * x1.x + w.b.y * x1.y + w.b.z * x1.z + w.b.w * x1.w;
}

__device__ __forceinline__ float row_dot(const f8 w[4], const float4* v4, int lane) {
    float acc = 0.f;
#pragma unroll
    for (int k = 0; k < 4; k++) {
        int c = (k * 32 + lane) * 2;
        acc += dot8(w[k], v4[c], v4[c + 1]);
    }
    return acc;
}

__device__ __forceinline__ float warp_sum(float acc) {
#pragma unroll
    for (int o = 16; o > 0; o >>= 1) acc += __shfl_down_sync(0xffffffffu, acc, o);
    return acc;
}

// LSTM elementwise for element j (torch gate order i, f, g, o)
__device__ __forceinline__ void act_phase(
        const float* __restrict__ part,
        const float* __restrict__ bih, const float* __restrict__ bhh,
        float cin, float& hout, float& cout, int j) {
    float gi = part[j]         + part[4096 + j]         + bih[j]         + bhh[j];
    float gf = part[j + H]     + part[4096 + j + H]     + bih[j + H]     + bhh[j + H];
    float gg = part[j + 2 * H] + part[4096 + j + 2 * H] + bih[j + 2 * H] + bhh[j + 2 * H];
    float go = part[j + 3 * H] + part[4096 + j + 3 * H] + bih[j + 3 * H] + bhh[j + 3 * H];
    cout = sigmoidf_fast(gf) * cin + sigmoidf_fast(gi) * tanhf(gg);
    hout = sigmoidf_fast(go) * tanhf(cout);
}

// ---------------------------------------------------------------------------
// Gates GEMV phase: 8192 virtual rows over NWARPS warps, 1 row per step.
// vr < 4096: Wih vs sx (relu'd x).  vr >= 4096: Whh vs sh (h).
// Zero-source rows: no loads, partial = 0.
// ---------------------------------------------------------------------------
__device__ __forceinline__ void gates_phase(
        const float* __restrict__ Wih, const float* __restrict__ Whh,
        const float4* sx4, const float4* sh4, float* __restrict__ part,
        int gw, int lane, bool xz, bool hz) {
    for (int vr = gw; vr < 8192; vr += NWARPS) {
        bool isA = vr < 4096;
        bool active = isA ? !xz : !hz;
        float acc = 0.f;
        if (active) {
            const float* W = (isA ? Wih : Whh) + (long)(vr & 4095) * H;
            f8 w[4];
            row_load(W, lane, w);
            acc = row_dot(w, isA ? sx4 : sh4, lane);
        }
        acc = warp_sum(acc);
        if (lane == 0) part[vr] = acc;
    }
}

// ---------------------------------------------------------------------------
// ONE persistent kernel, 512 threads/block, 296 blocks (2/SM), 3 grid barriers.
// ---------------------------------------------------------------------------
__global__ void __launch_bounds__(NT, 2) decoder_kernel(
        const int* __restrict__ id, const float* __restrict__ h0,
        const float* __restrict__ c0, const float* __restrict__ emb,
        const float* __restrict__ Wih, const float* __restrict__ Whh,
        const float* __restrict__ bih, const float* __restrict__ bhh,
        const float* __restrict__ Wout, const float* __restrict__ bout,
        float* __restrict__ out, int write_tail) {
    __shared__ float sx[H];
    __shared__ float sh[H];
    __shared__ float2 spair[16];
    __shared__ float s_lse;
    __shared__ int s_nzx, s_nzh;

    int t = threadIdx.x, lane = t & 31, warp = t >> 5, b = blockIdx.x;
    int gw = b * 16 + warp;
    const float4* sx4 = (const float4*)sx;
    const float4* sh4 = (const float4*)sh;

    // P0: stage relu(emb[id]) and h0; detect all-zero source vectors
    if (t == 0) { s_nzx = 0; s_nzh = 0; }
    __syncthreads();
    {
        const float* e = emb + (long)id[0] * H;
        float x0 = fmaxf(e[t], 0.f),  x1 = fmaxf(e[t + NT], 0.f);
        float hv0 = h0[t],            hv1 = h0[t + NT];
        sx[t] = x0; sx[t + NT] = x1;
        sh[t] = hv0; sh[t + NT] = hv1;
        if (x0 != 0.f || x1 != 0.f) s_nzx = 1;
        if (hv0 != 0.f || hv1 != 0.f) s_nzh = 1;
    }
    __syncthreads();

    // P1: layer-1 gates GEMV (Whh half skipped when h0 == 0)
    gates_phase(Wih, Whh, sx4, sh4, g_partA, gw, lane, !s_nzx, !s_nzh);
    gsync(0);

    // P2: act1 — redundant per block; c1 stays in registers
    float h1a, c1a, h1b, c1b;
    act_phase(g_partA, bih, bhh, c0[t],      h1a, c1a, t);
    act_phase(g_partA, bih, bhh, c0[t + NT], h1b, c1b, t + NT);
    __syncthreads();
    if (t == 0) { s_nzx = 0; s_nzh = 0; }
    __syncthreads();
    {
        float x0 = fmaxf(h1a, 0.f), x1 = fmaxf(h1b, 0.f);
        sx[t] = x0; sx[t + NT] = x1;
        sh[t] = h1a; sh[t + NT] = h1b;
        if (x0 != 0.f || x1 != 0.f) s_nzx = 1;
        if (h1a != 0.f || h1b != 0.f) s_nzh = 1;
    }
    __syncthreads();

    // P3: layer-2 gates GEMV (same weights per reference)
    gates_phase(Wih, Whh, sx4, sh4, g_partB, gw, lane, !s_nzx, !s_nzh);
    gsync(1);

    // P4: act2 — redundant per block; block 0 writes the (h, c) tail
    float h2a, c2a, h2b, c2b;
    act_phase(g_partB, bih, bhh, c1a, h2a, c2a, t);
    act_phase(g_partB, bih, bhh, c1b, h2b, c2b, t + NT);
    __syncthreads();
    sx[t] = h2a; sx[t + NT] = h2b;
    if (write_tail && b == 0) {
        out[VOCAB + t]          = h2a;
        out[VOCAB + t + NT]     = h2b;
        out[VOCAB + H + t]      = c2a;
        out[VOCAB + H + t + NT] = c2b;
    }
    __syncthreads();

    // P5: logits GEMV, 1 row per step, + per-warp online (max, sumexp)
    float m = -INFINITY, s = 0.f;
    for (int row = gw; row < VOCAB; row += NWARPS) {
        const float* p = Wout + (long)row * H;
        f8 w[4];
        row_load(p, lane, w);
        float acc = row_dot(w, sx4, lane);
        acc = warp_sum(acc);
        if (lane == 0) {
            float v = acc + bout[row];
            out[row] = v;
            merge_pair(m, s, v, 1.0f);
        }
    }
    if (lane == 0) spair[warp] = make_float2(m, s);
    __syncthreads();
    if (t == 0) {
        float mm = spair[0].x, ss = spair[0].y;
#pragma unroll
        for (int wq = 1; wq < 16; wq++) merge_pair(mm, ss, spair[wq].x, spair[wq].y);
        g_pairs[b] = make_float2(mm, ss);
    }
    gsync(2);

    // P6: every block redundantly reduces g_pairs (identical order => identical
    // bits), then subtracts lse from its slice of out.
    {
        float mm = -INFINITY, ss = 0.f;
        if (t < NB) { float2 p = g_pairs[t]; mm = p.x; ss = p.y; }
#pragma unroll
        for (int o = 16; o > 0; o >>= 1) {
            float m2 = __shfl_down_sync(0xffffffffu, mm, o);
            float s2 = __shfl_down_sync(0xffffffffu, ss, o);
            merge_pair(mm, ss, m2, s2);
        }
        if (lane == 0 && warp < 10) spair[warp] = make_float2(mm, ss);
        __syncthreads();
        if (t == 0) {
            mm = spair[0].x; ss = spair[0].y;
#pragma unroll
            for (int wq = 1; wq < 10; wq++) merge_pair(mm, ss, spair[wq].x, spair[wq].y);
            s_lse = mm + logf(ss);
        }
        __syncthreads();
    }
    int i = b * FIN_CHUNK + t;
    if (t < FIN_CHUNK && i < VOCAB) out[i] -= s_lse;
}

// ---------------------------------------------------------------------------
extern "C" void kernel_launch(void* const* d_in, const int* in_sizes, int n_in,
                              void* d_out, int out_size) {
    const int*   id   = (const int*)d_in[0];
    const float* h0   = (const float*)d_in[1];
    const float* c0   = (const float*)d_in[2];
    const float* emb  = (const float*)d_in[3];
    const float* Wih  = (const float*)d_in[4];
    const float* Whh  = (const float*)d_in[5];
    const float* bih  = (const float*)d_in[6];
    const float* bhh  = (const float*)d_in[7];
    const float* Wout = (const float*)d_in[8];
    const float* bout = (const float*)d_in[9];
    float* out = (float*)d_out;

    int write_tail = (out_size >= VOCAB + 2 * H) ? 1 : 0;

    decoder_kernel<<<NB, NT>>>(id, h0, c0, emb, Wih, Whh, bih, bhh,
                               Wout, bout, out, write_tail);
}